// round 4
// baseline (speedup 1.0000x reference)
#include <cuda_runtime.h>

#define B_ 128
#define T_ 1024
#define N_ 64
#define CPB 2   // chains per block

// Per-batch losses; reduced deterministically by a second kernel.
__device__ float g_loss[B_];

typedef unsigned long long u64;

__device__ __forceinline__ u64 pack2(float lo, float hi) {
    u64 d;
    asm("mov.b64 %0, {%1, %2};" : "=l"(d)
        : "r"(__float_as_uint(lo)), "r"(__float_as_uint(hi)));
    return d;
}
__device__ __forceinline__ float unpack_sum(u64 v) {
    unsigned a, b;
    asm("mov.b64 {%0, %1}, %2;" : "=r"(a), "=r"(b) : "l"(v));
    return __uint_as_float(a) + __uint_as_float(b);
}
__device__ __forceinline__ u64 ffma2(u64 a, u64 b, u64 c) {
    u64 d;
    asm("fma.rn.f32x2 %0, %1, %2, %3;" : "=l"(d) : "l"(a), "l"(b), "l"(c));
    return d;
}
__device__ __forceinline__ u64 fadd2(u64 a, u64 b) {
    u64 d;
    asm("add.rn.f32x2 %0, %1, %2;" : "=l"(d) : "l"(a), "l"(b));
    return d;
}

// 64 threads (2 warps), ONE state per thread, TWO chains per block interleaved
// in the instruction stream for ILP: chain B's FFMAs issue while chain A waits
// on LDS/barrier latency. Single __syncthreads per superstep (one step of each
// chain). Renormalization every 4th step.
__global__ void __launch_bounds__(N_, 1) crf_forward_kernel(
    const float* __restrict__ pot,     // (B,T,N)
    const int*   __restrict__ tags,    // (B,T)
    const int*   __restrict__ seqlen,  // (B,)
    const float* __restrict__ ck,      // (N,N)
    const float* __restrict__ sw)      // (B,)
{
    const int j  = threadIdx.x;
    const int b0 = blockIdx.x * CPB;

    __shared__ __align__(16) float abuf[2][CPB][N_];
    __shared__ float red[CPB][N_];

    // Column j of E = exp(chain_kernel), packed pairs; shared by both chains.
    u64 Ec[N_ / 2];
#pragma unroll
    for (int i = 0; i < N_ / 2; ++i)
        Ec[i] = pack2(__expf(ck[(2 * i) * N_ + j]),
                      __expf(ck[(2 * i + 1) * N_ + j]));

    const float* Pb[CPB];
    const int*   tagb[CPB];
    int          len[CPB];
#pragma unroll
    for (int c = 0; c < CPB; ++c) {
        Pb[c]   = pot  + (size_t)(b0 + c) * T_ * N_;
        tagb[c] = tags + (b0 + c) * T_;
        len[c]  = seqlen[b0 + c];
    }

    // ---------------- sequence scores (both chains) ----------------
    float seq_score[CPB];
#pragma unroll
    for (int c = 0; c < CPB; ++c) {
        float ss = 0.f;
        for (int t = j; t < len[c]; t += N_) {
            int tg = tagb[c][t];
            ss += Pb[c][t * N_ + tg];
            if (t >= 1) ss += ck[tagb[c][t - 1] * N_ + tg];
        }
        red[c][j] = ss;
    }
    __syncthreads();
#pragma unroll
    for (int off = N_ / 2; off >= 1; off >>= 1) {
        if (j < off) {
#pragma unroll
            for (int c = 0; c < CPB; ++c) red[c][j] += red[c][j + off];
        }
        __syncthreads();
    }
#pragma unroll
    for (int c = 0; c < CPB; ++c) seq_score[c] = red[c][0];

    // ---------------- forward scan ----------------
    float cacc[CPB], my_a[CPB], p_cur[CPB], p_nxt[CPB];
#pragma unroll
    for (int c = 0; c < CPB; ++c) {
        cacc[c] = Pb[c][0];
        my_a[c] = __expf(Pb[c][j] - cacc[c]);
        abuf[0][c][j] = my_a[c];
        p_cur[c] = Pb[c][1 * N_ + j];                  // len >= T/2 >= 2
        p_nxt[c] = Pb[c][min(2, len[c] - 1) * N_ + j];
    }
    __syncthreads();

    const int lenmax = max(len[0], len[1]);
    int cur = 0;
    for (int t = 1; t < lenmax; ++t) {
        const bool rn = (t & 3) == 0;
        float p_pref[CPB], scale[CPB], s[CPB];

#pragma unroll
        for (int c = 0; c < CPB; ++c) {
            p_pref[c] = Pb[c][min(t + 2, len[c] - 1) * N_ + j];
            float epot = __expf(p_cur[c]);

            const float* rd = abuf[cur][c];
            scale[c] = epot;
            if (rn) {                              // renormalize every 4th step
                float a0 = rd[0];                  // broadcast LDS
                scale[c] = __fdividef(1.0f, a0) * epot;
                if (t < len[c]) cacc[c] += __logf(a0);
            }

            // Full dot product: 16x LDS.128 (broadcast) + 32x FFMA2, 8 accs.
            const ulonglong2* a4 = (const ulonglong2*)rd;
            u64 acc[8];
#pragma unroll
            for (int m = 0; m < 8; ++m) acc[m] = 0ull;
#pragma unroll
            for (int k = 0; k < 16; ++k) {
                ulonglong2 v = a4[k];              // floats 4k..4k+3
                acc[(2 * k)     & 7] = ffma2(v.x, Ec[2 * k],     acc[(2 * k)     & 7]);
                acc[(2 * k + 1) & 7] = ffma2(v.y, Ec[2 * k + 1], acc[(2 * k + 1) & 7]);
            }
            acc[0] = fadd2(acc[0], acc[1]);
            acc[2] = fadd2(acc[2], acc[3]);
            acc[4] = fadd2(acc[4], acc[5]);
            acc[6] = fadd2(acc[6], acc[7]);
            acc[0] = fadd2(acc[0], acc[2]);
            acc[4] = fadd2(acc[4], acc[6]);
            acc[0] = fadd2(acc[0], acc[4]);
            s[c] = unpack_sum(acc[0]);
        }

#pragma unroll
        for (int c = 0; c < CPB; ++c) {
            if (t < len[c]) my_a[c] = s[c] * scale[c];   // frozen past len
            abuf[cur ^ 1][c][j] = my_a[c];
            p_cur[c] = p_nxt[c];
            p_nxt[c] = p_pref[c];
        }
        __syncthreads();
        cur ^= 1;
    }

    // ---------------- log norms + losses ----------------
#pragma unroll
    for (int c = 0; c < CPB; ++c) red[c][j] = abuf[cur][c][j];
    __syncthreads();
#pragma unroll
    for (int off = N_ / 2; off >= 1; off >>= 1) {
        if (j < off) {
#pragma unroll
            for (int c = 0; c < CPB; ++c) red[c][j] += red[c][j + off];
        }
        __syncthreads();
    }

    if (j == 0) {
#pragma unroll
        for (int c = 0; c < CPB; ++c) {
            float log_norm = cacc[c] + logf(red[c][0]);
            g_loss[b0 + c] = -(seq_score[c] - log_norm) * sw[b0 + c];
        }
    }
}

__global__ void crf_finalize_kernel(float* __restrict__ out)
{
    __shared__ float r[B_];
    int j = threadIdx.x;
    r[j] = g_loss[j];
    __syncthreads();
#pragma unroll
    for (int off = B_ / 2; off >= 1; off >>= 1) {
        if (j < off) r[j] += r[j + off];
        __syncthreads();
    }
    if (j == 0) out[0] = r[0] * (1.0f / (float)B_);
}

extern "C" void kernel_launch(void* const* d_in, const int* in_sizes, int n_in,
                              void* d_out, int out_size)
{
    const float* pot    = (const float*)d_in[0];
    const int*   tags   = (const int*)  d_in[1];
    const int*   seqlen = (const int*)  d_in[2];
    const float* ck     = (const float*)d_in[3];
    const float* sw     = (const float*)d_in[4];

    crf_forward_kernel<<<B_ / CPB, N_>>>(pot, tags, seqlen, ck, sw);
    crf_finalize_kernel<<<1, B_>>>((float*)d_out);
}

// round 5
// speedup vs baseline: 2.0745x; 2.0745x over previous
#include <cuda_runtime.h>

#define B_ 128
#define T_ 1024
#define N_ 64

// Per-batch losses; reduced deterministically by a second kernel.
__device__ float g_loss[B_];

typedef unsigned long long u64;

__device__ __forceinline__ u64 pack2(float lo, float hi) {
    u64 d;
    asm("mov.b64 %0, {%1, %2};" : "=l"(d)
        : "r"(__float_as_uint(lo)), "r"(__float_as_uint(hi)));
    return d;
}
__device__ __forceinline__ float unpack_sum(u64 v) {
    unsigned a, b;
    asm("mov.b64 {%0, %1}, %2;" : "=r"(a), "=r"(b) : "l"(v));
    return __uint_as_float(a) + __uint_as_float(b);
}
__device__ __forceinline__ u64 ffma2(u64 a, u64 b, u64 c) {
    u64 d;
    asm("fma.rn.f32x2 %0, %1, %2, %3;" : "=l"(d) : "l"(a), "l"(b), "l"(c));
    return d;
}
__device__ __forceinline__ u64 fadd2(u64 a, u64 b) {
    u64 d;
    asm("add.rn.f32x2 %0, %1, %2;" : "=l"(d) : "l"(a), "l"(b));
    return d;
}

// Full 64-MAC dot: 16x LDS.128 (broadcast) + 32x FFMA2, 8 accumulators.
__device__ __forceinline__ float dot64(const float* __restrict__ rd,
                                       const u64* __restrict__ Ec) {
    const ulonglong2* a4 = (const ulonglong2*)rd;
    u64 acc[8];
#pragma unroll
    for (int m = 0; m < 8; ++m) acc[m] = 0ull;
#pragma unroll
    for (int k = 0; k < 16; ++k) {
        ulonglong2 v = a4[k];
        acc[(2 * k)     & 7] = ffma2(v.x, Ec[2 * k],     acc[(2 * k)     & 7]);
        acc[(2 * k + 1) & 7] = ffma2(v.y, Ec[2 * k + 1], acc[(2 * k + 1) & 7]);
    }
    acc[0] = fadd2(acc[0], acc[1]);
    acc[2] = fadd2(acc[2], acc[3]);
    acc[4] = fadd2(acc[4], acc[5]);
    acc[6] = fadd2(acc[6], acc[7]);
    acc[0] = fadd2(acc[0], acc[2]);
    acc[4] = fadd2(acc[4], acc[6]);
    acc[0] = fadd2(acc[0], acc[4]);
    return unpack_sum(acc[0]);
}

// 128 threads: warps 0-1 run the FORWARD half-chain (alpha_t = D_t E^T a),
// warps 2-3 run the BACKWARD half-chain (w_{t-1} = E D_t w_t, w_L = 1),
// concurrently, meeting at m = ceil(L/2):  Z = sum_j alpha_m[j] * w_m[j].
// Exact algebraic split: halves the serial step count (1023 -> ~512).
__global__ void __launch_bounds__(2 * N_, 1) crf_forward_kernel(
    const float* __restrict__ pot,     // (B,T,N)
    const int*   __restrict__ tags,    // (B,T)
    const int*   __restrict__ seqlen,  // (B,)
    const float* __restrict__ ck,      // (N,N)
    const float* __restrict__ sw)      // (B,)
{
    const int tid = threadIdx.x;
    const int b   = blockIdx.x;
    const int grp = tid >> 6;          // 0 = forward, 1 = backward
    const int j   = tid & (N_ - 1);
    const int len = seqlen[b];
    const int L   = len - 1;           // last applied step index (len >= 512)

    __shared__ __align__(16) float buf[2][2][N_];  // [grp][double-buffer][state]
    __shared__ float red2[2 * N_];
    __shared__ float c_share;

    // E registers: forward needs column j of exp(ck); backward needs row j.
    u64 Ec[N_ / 2];
    if (grp == 0) {
#pragma unroll
        for (int i = 0; i < N_ / 2; ++i)
            Ec[i] = pack2(__expf(ck[(2 * i) * N_ + j]),
                          __expf(ck[(2 * i + 1) * N_ + j]));
    } else {
#pragma unroll
        for (int i = 0; i < N_ / 2; ++i)
            Ec[i] = pack2(__expf(ck[j * N_ + 2 * i]),
                          __expf(ck[j * N_ + 2 * i + 1]));
    }

    const float* Pb   = pot  + (size_t)b * T_ * N_;
    const int*   tagb = tags + b * T_;

    // ---------------- sequence score (all 128 threads) ----------------
    float ss = 0.f;
    for (int t = tid; t < len; t += 2 * N_) {
        int tg = tagb[t];
        ss += Pb[t * N_ + tg];
        if (t >= 1) ss += ck[tagb[t - 1] * N_ + tg];
    }
    red2[tid] = ss;
    __syncthreads();
#pragma unroll
    for (int off = N_; off >= 1; off >>= 1) {
        if (tid < off) red2[tid] += red2[tid + off];
        __syncthreads();
    }
    const float seq_score = red2[0];
    __syncthreads();

    // ---------------- split point ----------------
    const int stepsF = (L + 1) >> 1;       // forward steps t = 1..stepsF
    const int stepsB = L - stepsF;         // backward steps t = L..stepsF+1
    const int niter  = stepsF;             // stepsF >= stepsB >= stepsF-1

    // Init: forward alpha_0, backward v_L = D_L * 1 (both renormalized).
    float cacc, my_v, p_cur, p_nxt;
    if (grp == 0) {
        cacc = Pb[0];
        my_v = __expf(Pb[j] - cacc);
        p_cur = Pb[1 * N_ + j];
        p_nxt = Pb[2 * N_ + j];
    } else {
        cacc = Pb[L * N_];
        my_v = __expf(Pb[L * N_ + j] - cacc);
        p_cur = Pb[(L - 1) * N_ + j];
        p_nxt = Pb[(L - 2) * N_ + j];
    }
    buf[grp][0][j] = my_v;
    __syncthreads();

    int cur = 0;
    for (int i = 0; i < niter; ++i) {
        const float* rd = &buf[grp][cur][0];
        float val;
        if (grp == 0) {
            // forward: consumes epot at t = i+1; prefetch t = i+3 (clamped)
            float p_pref = Pb[min(i + 3, stepsF) * N_ + j];
            float mult = __expf(p_cur);
            if ((i & 3) == 0) {                    // renormalize every 4th
                float a0 = rd[0];
                mult *= __fdividef(1.0f, a0);
                cacc += __logf(a0);
            }
            float s = dot64(rd, Ec);
            val = s * mult;
            my_v = val;
            p_cur = p_nxt; p_nxt = p_pref;
        } else {
            // backward: iter i computes w at t = L-1-i; epot applied for the
            // NEXT step's D (t = L-1-i), except on the final active iter
            // (t reaches m: forward already owns D_m).
            const bool active      = i < stepsB;
            const bool last_active = i == stepsB - 1;
            float p_pref = Pb[max(L - 3 - i, 0) * N_ + j];
            float mult = last_active ? 1.0f : __expf(p_cur);
            if (((i & 3) == 0) && active) {
                float a0 = rd[0];
                mult *= __fdividef(1.0f, a0);
                cacc += __logf(a0);
            }
            float s = dot64(rd, Ec);
            val = s * mult;
            if (active) my_v = val;                // freeze when done
            p_cur = p_nxt; p_nxt = p_pref;
        }
        buf[grp][cur ^ 1][j] = my_v;
        __syncthreads();
        cur ^= 1;
    }

    // ---------------- combine: Z = sum_j alpha_m[j] * w_m[j] ----------------
    if (tid == N_) c_share = cacc;            // backward group's log-offset
    if (grp == 0) red2[j] = buf[0][cur][j] * buf[1][cur][j];
    __syncthreads();
#pragma unroll
    for (int off = N_ / 2; off >= 1; off >>= 1) {
        if (tid < off) red2[tid] += red2[tid + off];
        __syncthreads();
    }

    if (tid == 0) {
        float log_norm = cacc + c_share + logf(red2[0]);
        g_loss[b] = -(seq_score - log_norm) * sw[b];
    }
}

__global__ void crf_finalize_kernel(float* __restrict__ out)
{
    __shared__ float r[B_];
    int j = threadIdx.x;
    r[j] = g_loss[j];
    __syncthreads();
#pragma unroll
    for (int off = B_ / 2; off >= 1; off >>= 1) {
        if (j < off) r[j] += r[j + off];
        __syncthreads();
    }
    if (j == 0) out[0] = r[0] * (1.0f / (float)B_);
}

extern "C" void kernel_launch(void* const* d_in, const int* in_sizes, int n_in,
                              void* d_out, int out_size)
{
    const float* pot    = (const float*)d_in[0];
    const int*   tags   = (const int*)  d_in[1];
    const int*   seqlen = (const int*)  d_in[2];
    const float* ck     = (const float*)d_in[3];
    const float* sw     = (const float*)d_in[4];

    crf_forward_kernel<<<B_, 2 * N_>>>(pot, tags, seqlen, ck, sw);
    crf_finalize_kernel<<<1, B_>>>((float*)d_out);
}

// round 6
// speedup vs baseline: 2.5403x; 1.2245x over previous
#include <cuda_runtime.h>

#define B_ 128
#define T_ 1024
#define N_ 64

// Per-batch losses; reduced deterministically by a second kernel.
__device__ float g_loss[B_];

typedef unsigned long long u64;

__device__ __forceinline__ u64 pack2(float lo, float hi) {
    u64 d;
    asm("mov.b64 %0, {%1, %2};" : "=l"(d)
        : "r"(__float_as_uint(lo)), "r"(__float_as_uint(hi)));
    return d;
}
__device__ __forceinline__ float unpack_sum(u64 v) {
    unsigned a, b;
    asm("mov.b64 {%0, %1}, %2;" : "=r"(a), "=r"(b) : "l"(v));
    return __uint_as_float(a) + __uint_as_float(b);
}
__device__ __forceinline__ u64 ffma2(u64 a, u64 b, u64 c) {
    u64 d;
    asm("fma.rn.f32x2 %0, %1, %2, %3;" : "=l"(d) : "l"(a), "l"(b), "l"(c));
    return d;
}
__device__ __forceinline__ u64 fadd2(u64 a, u64 b) {
    u64 d;
    asm("add.rn.f32x2 %0, %1, %2;" : "=l"(d) : "l"(a), "l"(b));
    return d;
}

// Full 64-MAC dot: 16x LDS.128 (broadcast) + 32x FFMA2, 8 accumulators.
__device__ __forceinline__ float dot64(const float* __restrict__ rd,
                                       const u64* __restrict__ Ec) {
    const ulonglong2* a4 = (const ulonglong2*)rd;
    u64 acc[8];
#pragma unroll
    for (int m = 0; m < 8; ++m) acc[m] = 0ull;
#pragma unroll
    for (int k = 0; k < 16; ++k) {
        ulonglong2 v = a4[k];
        acc[(2 * k)     & 7] = ffma2(v.x, Ec[2 * k],     acc[(2 * k)     & 7]);
        acc[(2 * k + 1) & 7] = ffma2(v.y, Ec[2 * k + 1], acc[(2 * k + 1) & 7]);
    }
    acc[0] = fadd2(acc[0], acc[1]);
    acc[2] = fadd2(acc[2], acc[3]);
    acc[4] = fadd2(acc[4], acc[5]);
    acc[6] = fadd2(acc[6], acc[7]);
    acc[0] = fadd2(acc[0], acc[2]);
    acc[4] = fadd2(acc[4], acc[6]);
    acc[0] = fadd2(acc[0], acc[4]);
    return unpack_sum(acc[0]);
}

// One scan step, branch-free, group-uniform. RENORM is compile-time.
#define STEP(SRC, DST, RENORM)                                           \
    {                                                                    \
        float p_pref = Pb[max(pidx, 0) * N_ + j];                        \
        pidx += pinc;                                                    \
        float mult = __expf(p_cur);                                      \
        if (RENORM) {                                                    \
            float a0 = (SRC)[0];                                         \
            mult *= __fdividef(1.0f, a0);                                \
            cacc += __logf(a0);                                          \
        }                                                                \
        float s = dot64((SRC), Ec);                                      \
        my_v = s * mult;                                                 \
        (DST)[j] = my_v;                                                 \
        asm volatile("bar.sync %0, 64;" :: "r"(barid) : "memory");       \
        p_cur = p_nxt;                                                   \
        p_nxt = p_pref;                                                  \
    }

// 128 threads: warps 0-1 FORWARD half-chain, warps 2-3 BACKWARD half-chain,
// meeting at m = ceil(L/2): Z = sum_j alpha_m[j] * w_m[j]. Main loop is a
// single uniform instruction stream (pointer+stride parameterized), unrolled
// 4x with static renorm placement; per-group named barriers decouple groups.
__global__ void __launch_bounds__(2 * N_, 1) crf_forward_kernel(
    const float* __restrict__ pot,     // (B,T,N)
    const int*   __restrict__ tags,    // (B,T)
    const int*   __restrict__ seqlen,  // (B,)
    const float* __restrict__ ck,      // (N,N)
    const float* __restrict__ sw)      // (B,)
{
    const int tid = threadIdx.x;
    const int b   = blockIdx.x;
    const int grp = tid >> 6;          // 0 = forward, 1 = backward
    const int j   = tid & (N_ - 1);
    const int len = seqlen[b];
    const int L   = len - 1;           // len >= T/2 = 512
    const int barid = 1 + grp;

    __shared__ __align__(16) float buf[2][2][N_];  // [grp][parity][state]
    __shared__ float red2[2 * N_];
    __shared__ float c_share;

    // E registers: forward = column j of exp(ck); backward = row j.
    u64 Ec[N_ / 2];
    if (grp == 0) {
#pragma unroll
        for (int i = 0; i < N_ / 2; ++i)
            Ec[i] = pack2(__expf(ck[(2 * i) * N_ + j]),
                          __expf(ck[(2 * i + 1) * N_ + j]));
    } else {
#pragma unroll
        for (int i = 0; i < N_ / 2; ++i)
            Ec[i] = pack2(__expf(ck[j * N_ + 2 * i]),
                          __expf(ck[j * N_ + 2 * i + 1]));
    }

    const float* Pb   = pot  + (size_t)b * T_ * N_;
    const int*   tagb = tags + b * T_;

    // ---------------- sequence score ----------------
    float ss = 0.f;
    for (int t = tid; t < len; t += 2 * N_) {
        int tg = tagb[t];
        ss += Pb[t * N_ + tg];
        if (t >= 1) ss += ck[tagb[t - 1] * N_ + tg];
    }
    red2[tid] = ss;
    __syncthreads();
#pragma unroll
    for (int off = N_; off >= 1; off >>= 1) {
        if (tid < off) red2[tid] += red2[tid + off];
        __syncthreads();
    }
    const float seq_score = red2[0];
    __syncthreads();

    const int stepsF = (L + 1) >> 1;   // forward applies t = 1..stepsF
    const int stepsB = L - stepsF;     // backward applies t = L..stepsF+1
    const int niter  = stepsF;

    // ---------------- init ----------------
    float cacc, my_v, p_cur, p_nxt;
    int pidx, pinc;
    if (grp == 0) {
        cacc  = Pb[0];
        my_v  = __expf(Pb[j] - cacc);
        p_cur = Pb[1 * N_ + j];
        p_nxt = Pb[2 * N_ + j];
        pidx  = 3;   pinc = 1;
    } else {
        cacc  = Pb[L * N_];
        my_v  = __expf(Pb[L * N_ + j] - cacc);
        p_cur = Pb[(L - 1) * N_ + j];
        p_nxt = Pb[(L - 2) * N_ + j];
        pidx  = L - 3;   pinc = -1;
    }
    float* b0 = &buf[grp][0][0];
    float* b1 = &buf[grp][1][0];
    b0[j] = my_v;
    asm volatile("bar.sync %0, 64;" :: "r"(barid) : "memory");

    // ---------------- main loop: uniform, unrolled x4 ----------------
    // In [0, nmain): backward is strictly active and not last_active.
    const int nmain = (niter >= 3) ? ((niter - 2) & ~3) : 0;
    for (int i = 0; i < nmain; i += 4) {
        STEP(b0, b1, true)
        STEP(b1, b0, false)
        STEP(b0, b1, false)
        STEP(b1, b0, false)
    }

    // ---------------- tail (2..5 iters, predicated) ----------------
    int cur = 0;
    for (int i = nmain; i < niter; ++i) {
        float* src = cur ? b1 : b0;
        float* dst = cur ? b0 : b1;
        const bool active      = (grp == 0) || (i < stepsB);
        const bool last_active = (grp == 1) && (i == stepsB - 1);
        float p_pref = Pb[max(pidx, 0) * N_ + j];
        pidx += pinc;
        float mult = last_active ? 1.0f : __expf(p_cur);
        if (((i & 3) == 0) && active) {
            float a0 = src[0];
            mult *= __fdividef(1.0f, a0);
            cacc += __logf(a0);
        }
        float s = dot64(src, Ec);
        if (active) my_v = s * mult;
        dst[j] = my_v;
        asm volatile("bar.sync %0, 64;" :: "r"(barid) : "memory");
        p_cur = p_nxt;
        p_nxt = p_pref;
        cur ^= 1;
    }

    // ---------------- combine: Z = sum_j alpha_m[j] * w_m[j] ----------------
    if (tid == N_) c_share = cacc;            // backward group's log-offset
    __syncthreads();
    if (grp == 0) red2[j] = buf[0][cur][j] * buf[1][cur][j];
    __syncthreads();
#pragma unroll
    for (int off = N_ / 2; off >= 1; off >>= 1) {
        if (tid < off) red2[tid] += red2[tid + off];
        __syncthreads();
    }

    if (tid == 0) {
        float log_norm = cacc + c_share + logf(red2[0]);
        g_loss[b] = -(seq_score - log_norm) * sw[b];
    }
}

__global__ void crf_finalize_kernel(float* __restrict__ out)
{
    __shared__ float r[B_];
    int j = threadIdx.x;
    r[j] = g_loss[j];
    __syncthreads();
#pragma unroll
    for (int off = B_ / 2; off >= 1; off >>= 1) {
        if (j < off) r[j] += r[j + off];
        __syncthreads();
    }
    if (j == 0) out[0] = r[0] * (1.0f / (float)B_);
}

extern "C" void kernel_launch(void* const* d_in, const int* in_sizes, int n_in,
                              void* d_out, int out_size)
{
    const float* pot    = (const float*)d_in[0];
    const int*   tags   = (const int*)  d_in[1];
    const int*   seqlen = (const int*)  d_in[2];
    const float* ck     = (const float*)d_in[3];
    const float* sw     = (const float*)d_in[4];

    crf_forward_kernel<<<B_, 2 * N_>>>(pot, tags, seqlen, ck, sw);
    crf_finalize_kernel<<<1, B_>>>((float*)d_out);
}